// round 12
// baseline (speedup 1.0000x reference)
#include <cuda_runtime.h>
#include <cstddef>

// Problem constants
#define NB   16
#define NT   64
#define NF0  8
#define NN   100
#define BT   (NB * NT)            // 1024
#define ROWSTRIDE (NF0 * NN)      // 800 floats per (b,t) slice
#define SLAB ((size_t)BT * ROWSTRIDE)  // 819200 floats per k-slab

__device__ float g_z[15 * BT * ROWSTRIDE];   // slabs k=1..15 (~49 MB)
__device__ int   g_flag[BT];                 // wavefront progress: max k done

// ---- packed f32x2 helpers ----
typedef unsigned long long ull;
__device__ __forceinline__ ull pack2(float lo, float hi) {
    ull r; asm("mov.b64 %0, {%1,%2};" : "=l"(r) : "f"(lo), "f"(hi)); return r;
}
__device__ __forceinline__ void unpack2(ull v, float& lo, float& hi) {
    asm("mov.b64 {%0,%1}, %2;" : "=f"(lo), "=f"(hi) : "l"(v));
}
__device__ __forceinline__ ull ffma2(ull a, ull b, ull c) {
    ull d; asm("fma.rn.f32x2 %0, %1, %2, %3;" : "=l"(d) : "l"(a), "l"(b), "l"(c));
    return d;
}

// ---------------------------------------------------------------------------
__global__ void reset_flags_kernel()
{
    int i = blockIdx.x * 256 + threadIdx.x;
    if (i < BT) g_flag[i] = 0;
}

// ---------------------------------------------------------------------------
// Wavefront diffusion: block = (b,t), t-major ids (deps point to lower ids).
// S[b,t] loaded to smem ONCE, reused for all k=1..min(15,t):
//   z_k[b,t] = z_{k-1}[b,t-1] @ S[b,t]
// Inter-block handoff via g_flag (L2 atomics) + __ldcg reads.
// Inner compute = R9's transposed mapping (thread = column m).
// ---------------------------------------------------------------------------
__global__ __launch_bounds__(128)
void diffuse_wave_kernel(const float* __restrict__ x,
                         const float* __restrict__ S)
{
    int id = blockIdx.x;
    int t  = id >> 4;              // t-major: all chains start immediately
    int b  = id & 15;
    if (t == 0) return;            // no steps (z_k[b,0] all in zero region)
    int bt  = b * 64 + t;
    int len = t < 15 ? t : 15;
    int tid = threadIdx.x;

    extern __shared__ float smw[];
    float* Ssh = smw;              // [n*100 + m], 10000 floats
    float* At  = smw + NN * NN;    // [n*8 + f],   800 floats

    {   // load S[b,t] once (coalesced)
        const float* Sg = S + (size_t)bt * (NN * NN);
        for (int i = tid; i < NN * NN; i += 128) Ssh[i] = Sg[i];
    }

    const float* xsrc = x + (size_t)(bt - 1) * ROWSTRIDE;

    for (int k = 1; k <= len; k++) {
        // ---- wait for producer (b, t-1) to finish step k-1 ----
        if (k > 1) {
            if (tid == 0) {
                while (atomicAdd(&g_flag[bt - 1], 0) < k - 1)
                    __nanosleep(40);
                __threadfence();
            }
            __syncthreads();
        }

        // ---- load A = z_{k-1}[b,t-1] (or x) transposed into smem ----
        if (k == 1) {
            for (int i = tid; i < ROWSTRIDE; i += 128) {
                int f = i / NN, n = i % NN;
                At[n * 8 + f] = xsrc[i];
            }
        } else {
            const float* src = g_z + (size_t)(k - 2) * SLAB
                             + (size_t)(bt - 1) * ROWSTRIDE;
            for (int i = tid; i < ROWSTRIDE; i += 128) {
                int f = i / NN, n = i % NN;
                At[n * 8 + f] = __ldcg(src + i);   // L2-coherent read
            }
        }
        __syncthreads();

        // ---- compute column m of all 8 f-rows ----
        if (tid < 100) {
            int m = tid;
            ull a01 = 0ull, a23 = 0ull, a45 = 0ull, a67 = 0ull;
            #pragma unroll 4
            for (int n = 0; n < NN; n++) {
                float s = Ssh[n * NN + m];         // conflict-free
                ull s2 = pack2(s, s);
                const ull* ar = reinterpret_cast<const ull*>(At + n * 8);
                a01 = ffma2(ar[0], s2, a01);
                a23 = ffma2(ar[1], s2, a23);
                a45 = ffma2(ar[2], s2, a45);
                a67 = ffma2(ar[3], s2, a67);
            }
            float* dst = g_z + (size_t)(k - 1) * SLAB
                       + (size_t)bt * ROWSTRIDE + m;
            float v0, v1;
            unpack2(a01, v0, v1); dst[0 * NN] = v0; dst[1 * NN] = v1;
            unpack2(a23, v0, v1); dst[2 * NN] = v0; dst[3 * NN] = v1;
            unpack2(a45, v0, v1); dst[4 * NN] = v0; dst[5 * NN] = v1;
            unpack2(a67, v0, v1); dst[6 * NN] = v0; dst[7 * NN] = v1;
        }
        __syncthreads();

        // ---- publish step k ----
        if (tid == 0) {
            __threadfence();
            atomicExch(&g_flag[bt], k);
        }
    }
}

// ---------------------------------------------------------------------------
// Fused head (proven R9 scalar version): gather z [8][16] -> conv1+relu+pool2
// -> conv2+relu+pool2 -> fc1+relu -> fc2 -> out[b,t,o,n]
// 32 rows/block, 256 threads, 2 blocks/SM, stage-overlaid smem.
// ---------------------------------------------------------------------------
#define ZS   129
#define Y1S  193
#define Y2S  129
#define HS   65
#define OFF_HSH 4128
#define OFF_Y1  6208
#define OFF_W1  12384
#define OFF_B1  13408
#define OFF_W2  13440
#define SMEM_FLOATS 22085

__global__ __launch_bounds__(256, 2)
void head_kernel(const float* __restrict__ x,
                 const float* __restrict__ w1g, const float* __restrict__ b1g,
                 const float* __restrict__ w2g, const float* __restrict__ b2g,
                 const float* __restrict__ f1wg, const float* __restrict__ f1bg,
                 const float* __restrict__ f2wg, const float* __restrict__ f2bg,
                 float* __restrict__ out)
{
    extern __shared__ float sm[];
    float* zsh  = sm;
    float* y2sh = sm;                 // reuses zsh region after conv1
    float* hsh  = sm + OFF_HSH;
    float* y1sh = sm + OFF_Y1;
    float* w1sh = sm + OFF_W1;
    float* b1sh = sm + OFF_B1;

    int tid  = threadIdx.x;
    int row0 = blockIdx.x * 32;       // global row = (b*T + t)*N + n

    // ---- stage 0: gather z tile (32 rows x 8 f x 16 k) + conv weights ----
    for (int i = tid; i < 4096; i += 256) {
        int r  = i & 31;
        int kf = i >> 5;
        int f  = kf >> 4;
        int k  = kf & 15;
        int R  = row0 + r;
        int n  = R % NN;
        int bt = R / NN;
        float v;
        if (k == 0) {
            v = x[(size_t)bt * ROWSTRIDE + f * NN + n];
        } else if ((bt & 63) < k) {
            v = 0.f;                  // triangular zero region (never stored)
        } else {
            v = g_z[(size_t)(k - 1) * SLAB + (size_t)bt * ROWSTRIDE + f * NN + n];
        }
        zsh[r * ZS + f * 16 + k] = v;
    }
    for (int i = tid; i < 1024; i += 256) w1sh[i] = w1g[i];
    if (tid < 32) b1sh[tid] = b1g[tid];
    {
        float* w2sh = sm + OFF_W2;
        for (int i = tid; i < 6144; i += 256) w2sh[i] = w2g[i];
        if (tid < 64) w2sh[6144 + tid] = b2g[tid];
    }
    __syncthreads();

    // ---- conv1 + relu + maxpool2 : thread = (r, 4 channels) ----
    {
        int r = tid & 31, fg = tid >> 5;
        float acc[4][12];
        #pragma unroll
        for (int c = 0; c < 4; c++)
            #pragma unroll
            for (int l = 0; l < 12; l++) acc[c][l] = 0.f;

        #pragma unroll 2
        for (int f0 = 0; f0 < 8; f0++) {
            float a[16];
            #pragma unroll
            for (int i = 0; i < 16; i++) a[i] = zsh[r * ZS + f0 * 16 + i];
            #pragma unroll
            for (int kk = 0; kk < 4; kk++) {
                #pragma unroll
                for (int c = 0; c < 4; c++) {
                    float w = w1sh[(fg * 4 + c) * 32 + f0 * 4 + kk];
                    #pragma unroll
                    for (int l = 0; l < 12; l++)
                        acc[c][l] = fmaf(a[l + kk], w, acc[c][l]);
                }
            }
        }
        #pragma unroll
        for (int c = 0; c < 4; c++) {
            int f1 = fg * 4 + c;
            float bb = b1sh[f1];
            #pragma unroll
            for (int lp = 0; lp < 6; lp++) {
                float v0 = fmaxf(acc[c][2 * lp]     + bb, 0.f);
                float v1 = fmaxf(acc[c][2 * lp + 1] + bb, 0.f);
                y1sh[r * Y1S + f1 * 6 + lp] = fmaxf(v0, v1);
            }
        }
    }
    __syncthreads();

    // ---- conv2 + relu + maxpool2 : thread = (r, 8 channels) ----
    {
        const float* w2sh = sm + OFF_W2;
        const float* b2sh = w2sh + 6144;
        int r = tid & 31, fg = tid >> 5;
        float acc[8][4];
        #pragma unroll
        for (int c = 0; c < 8; c++)
            #pragma unroll
            for (int l = 0; l < 4; l++) acc[c][l] = 0.f;

        #pragma unroll 4
        for (int f1 = 0; f1 < 32; f1++) {
            float a[6];
            #pragma unroll
            for (int i = 0; i < 6; i++) a[i] = y1sh[r * Y1S + f1 * 6 + i];
            #pragma unroll
            for (int kk = 0; kk < 3; kk++) {
                #pragma unroll
                for (int c = 0; c < 8; c++) {
                    float w = w2sh[(fg * 8 + c) * 96 + f1 * 3 + kk];
                    #pragma unroll
                    for (int l = 0; l < 4; l++)
                        acc[c][l] = fmaf(a[l + kk], w, acc[c][l]);
                }
            }
        }
        #pragma unroll
        for (int c = 0; c < 8; c++) {
            int f2 = fg * 8 + c;
            float bb = b2sh[f2];
            float v0 = fmaxf(fmaxf(acc[c][0] + bb, 0.f), fmaxf(acc[c][1] + bb, 0.f));
            float v1 = fmaxf(fmaxf(acc[c][2] + bb, 0.f), fmaxf(acc[c][3] + bb, 0.f));
            y2sh[r * Y2S + f2 * 2 + 0] = v0;
            y2sh[r * Y2S + f2 * 2 + 1] = v1;
        }
    }
    __syncthreads();

    // ---- load fc weights (overwrites conv2 weight region) ----
    {
        float* fcr = sm + OFF_W2;
        for (int i = tid; i < 8192; i += 256) {
            int j = i >> 7, d = i & 127;
            fcr[j * 129 + d] = f1wg[i];
        }
        if (tid < 64) fcr[8256 + tid] = f1bg[tid];
        for (int i = tid; i < 320; i += 256) fcr[8320 + i] = f2wg[i];
        if (tid < 5) fcr[8640 + tid] = f2bg[tid];
    }
    __syncthreads();

    // ---- fc1 + relu : 128 threads, thread tile 4 rows x 4 hidden ----
    if (tid < 128) {
        const float* fc1sh = sm + OFF_W2;
        const float* fb    = fc1sh + 8256;
        int rg = tid & 7;
        int hg = tid >> 3;
        float acc[4][4];
        #pragma unroll
        for (int i = 0; i < 4; i++)
            #pragma unroll
            for (int j = 0; j < 4; j++) acc[i][j] = 0.f;

        #pragma unroll 4
        for (int d = 0; d < 128; d++) {
            float a0 = y2sh[(rg * 4 + 0) * Y2S + d];
            float a1 = y2sh[(rg * 4 + 1) * Y2S + d];
            float a2 = y2sh[(rg * 4 + 2) * Y2S + d];
            float a3 = y2sh[(rg * 4 + 3) * Y2S + d];
            float w0 = fc1sh[(hg * 4 + 0) * 129 + d];
            float w1 = fc1sh[(hg * 4 + 1) * 129 + d];
            float w2 = fc1sh[(hg * 4 + 2) * 129 + d];
            float w3 = fc1sh[(hg * 4 + 3) * 129 + d];
            acc[0][0] = fmaf(a0, w0, acc[0][0]); acc[0][1] = fmaf(a0, w1, acc[0][1]);
            acc[0][2] = fmaf(a0, w2, acc[0][2]); acc[0][3] = fmaf(a0, w3, acc[0][3]);
            acc[1][0] = fmaf(a1, w0, acc[1][0]); acc[1][1] = fmaf(a1, w1, acc[1][1]);
            acc[1][2] = fmaf(a1, w2, acc[1][2]); acc[1][3] = fmaf(a1, w3, acc[1][3]);
            acc[2][0] = fmaf(a2, w0, acc[2][0]); acc[2][1] = fmaf(a2, w1, acc[2][1]);
            acc[2][2] = fmaf(a2, w2, acc[2][2]); acc[2][3] = fmaf(a2, w3, acc[2][3]);
            acc[3][0] = fmaf(a3, w0, acc[3][0]); acc[3][1] = fmaf(a3, w1, acc[3][1]);
            acc[3][2] = fmaf(a3, w2, acc[3][2]); acc[3][3] = fmaf(a3, w3, acc[3][3]);
        }
        #pragma unroll
        for (int i = 0; i < 4; i++)
            #pragma unroll
            for (int j = 0; j < 4; j++)
                hsh[(rg * 4 + i) * HS + hg * 4 + j] =
                    fmaxf(acc[i][j] + fb[hg * 4 + j], 0.f);
    }
    __syncthreads();

    // ---- fc2 + transposed output write: out[b,t,o,n] ----
    if (tid < 160) {
        const float* fc2w = sm + OFF_W2 + 8320;
        const float* fc2b = sm + OFF_W2 + 8640;
        int r = tid & 31, o = tid >> 5;
        float acc = fc2b[o];
        #pragma unroll 8
        for (int j = 0; j < 64; j++)
            acc = fmaf(hsh[r * HS + j], fc2w[o * 64 + j], acc);
        int R  = row0 + r;
        int n  = R % NN;
        int bt = R / NN;
        out[((size_t)bt * 5 + o) * NN + n] = acc;
    }
}

// ---------------------------------------------------------------------------
extern "C" void kernel_launch(void* const* d_in, const int* in_sizes, int n_in,
                              void* d_out, int out_size)
{
    const float* x   = (const float*)d_in[0];
    const float* S   = (const float*)d_in[1];
    const float* w1  = (const float*)d_in[2];
    const float* b1  = (const float*)d_in[3];
    const float* w2  = (const float*)d_in[4];
    const float* b2  = (const float*)d_in[5];
    const float* f1w = (const float*)d_in[6];
    const float* f1b = (const float*)d_in[7];
    const float* f2w = (const float*)d_in[8];
    const float* f2b = (const float*)d_in[9];
    float* out = (float*)d_out;

    reset_flags_kernel<<<(BT + 255) / 256, 256>>>();

    size_t wsmem = (size_t)(NN * NN + ROWSTRIDE) * sizeof(float);  // 43.2 KB
    cudaFuncSetAttribute(diffuse_wave_kernel,
                         cudaFuncAttributeMaxDynamicSharedMemorySize, (int)wsmem);
    diffuse_wave_kernel<<<BT, 128, wsmem>>>(x, S);

    size_t smem = (size_t)SMEM_FLOATS * sizeof(float);
    cudaFuncSetAttribute(head_kernel,
                         cudaFuncAttributeMaxDynamicSharedMemorySize, (int)smem);
    head_kernel<<<(NB * NT * NN) / 32, 256, smem>>>(
        x, w1, b1, w2, b2, f1w, f1b, f2w, f2b, out);
}

// round 14
// speedup vs baseline: 1.1183x; 1.1183x over previous
#include <cuda_runtime.h>
#include <cstddef>
#include <cstdint>

// Problem constants
#define NB   16
#define NT   64
#define NF0  8
#define NN   100
#define BT   (NB * NT)            // 1024
#define ROWSTRIDE (NF0 * NN)      // 800 floats per (b,t) slice
#define SLAB ((size_t)BT * ROWSTRIDE)  // 819200 floats per k-slab

__device__ float g_z[15 * BT * ROWSTRIDE];   // slabs k=1..15 (~49 MB)

// ---- packed f32x2 helpers (diffusion only) ----
typedef unsigned long long ull;
__device__ __forceinline__ ull pack2(float lo, float hi) {
    ull r; asm("mov.b64 %0, {%1,%2};" : "=l"(r) : "f"(lo), "f"(hi)); return r;
}
__device__ __forceinline__ void unpack2(ull v, float& lo, float& hi) {
    asm("mov.b64 {%0,%1}, %2;" : "=f"(lo), "=f"(hi) : "l"(v));
}
__device__ __forceinline__ ull ffma2(ull a, ull b, ull c) {
    ull d; asm("fma.rn.f32x2 %0, %1, %2, %3;" : "=l"(d) : "l"(a), "l"(b), "l"(c));
    return d;
}

// ---- tf32 helpers ----
__device__ __forceinline__ uint32_t tf32_of(float x) {
    uint32_t u; asm("cvt.rna.tf32.f32 %0, %1;" : "=r"(u) : "f"(x)); return u;
}
__device__ __forceinline__ void tf32_split(float x, uint32_t& hi, uint32_t& lo) {
    hi = tf32_of(x);
    lo = tf32_of(x - __uint_as_float(hi));
}
__device__ __forceinline__ void mma_tf32(
    float& d0, float& d1, float& d2, float& d3,
    uint32_t a0, uint32_t a1, uint32_t a2, uint32_t a3,
    uint32_t b0, uint32_t b1)
{
    asm volatile(
        "mma.sync.aligned.m16n8k8.row.col.f32.tf32.tf32.f32 "
        "{%0,%1,%2,%3}, {%4,%5,%6,%7}, {%8,%9}, {%0,%1,%2,%3};"
        : "+f"(d0), "+f"(d1), "+f"(d2), "+f"(d3)
        : "r"(a0), "r"(a1), "r"(a2), "r"(a3), "r"(b0), "r"(b1));
}

// ---------------------------------------------------------------------------
// Diffusion step k (R9 version — measured best): thread = column m (tid<100),
// owns all 8 f accumulators (4 x f32x2); A transposed in smem.
// ---------------------------------------------------------------------------
__global__ __launch_bounds__(128)
void diffuse_step_kernel(const float* __restrict__ x,
                         const float* __restrict__ S,
                         int k)
{
    int bt  = blockIdx.x;
    int t   = bt & 63;
    if (t < k) return;
    int tid = threadIdx.x;

    const float* src = (k == 1)
        ? (x + (size_t)(bt - 1) * ROWSTRIDE)
        : (g_z + (size_t)(k - 2) * SLAB + (size_t)(bt - 1) * ROWSTRIDE);

    __shared__ float At[NN * NF0];            // [n][f]
    for (int i = tid; i < ROWSTRIDE; i += 128) {
        int f = i / NN, n = i % NN;
        At[n * 8 + f] = src[i];
    }
    __syncthreads();

    if (tid < 100) {
        int m = tid;
        const float* Sp = S + (size_t)bt * (NN * NN) + m;

        ull a01 = 0ull, a23 = 0ull, a45 = 0ull, a67 = 0ull;
        #pragma unroll 4
        for (int n = 0; n < NN; n++) {
            float s = Sp[(size_t)n * NN];
            ull s2 = pack2(s, s);
            const ull* ar = reinterpret_cast<const ull*>(At + n * 8);
            a01 = ffma2(ar[0], s2, a01);
            a23 = ffma2(ar[1], s2, a23);
            a45 = ffma2(ar[2], s2, a45);
            a67 = ffma2(ar[3], s2, a67);
        }
        float* dst = g_z + (size_t)(k - 1) * SLAB + (size_t)bt * ROWSTRIDE + m;
        float v0, v1;
        unpack2(a01, v0, v1); dst[0 * NN] = v0; dst[1 * NN] = v1;
        unpack2(a23, v0, v1); dst[2 * NN] = v0; dst[3 * NN] = v1;
        unpack2(a45, v0, v1); dst[4 * NN] = v0; dst[5 * NN] = v1;
        unpack2(a67, v0, v1); dst[6 * NN] = v0; dst[7 * NN] = v1;
    }
}

// ---------------------------------------------------------------------------
// Fused head: gather z -> conv1 (scalar) -> CONV2 VIA 3xTF32 MMA -> fc1/fc2
// (scalar). 32 rows/block, 256 threads, 2 blocks/SM.
//
// Smem (floats):
//  [0,4128)       zsh (32x129)  -> reused as y2sh (32x129)
//  [4128,6208)    hsh (32x65)
//  [6208,12384)   y1sh (32x193)
//  [12384,13408)  w1   [13408,13440) b1
//  [13440,19840)  w2hi (64 x 100, tf32 bits)    } dead after conv2,
//  [19840,26240)  w2lo (64 x 100, tf32 bits)    } reused for fc weights:
//  [26240,26304)  b2                              fc1w@13440 (64x129),
//                                                 fc1b@+8256, fc2w@+8320,
//                                                 fc2b@+8640
// ---------------------------------------------------------------------------
#define ZS   129
#define Y1S  193
#define Y2S  129
#define HS   65
#define OFF_HSH  4128
#define OFF_Y1   6208
#define OFF_W1   12384
#define OFF_B1   13408
#define OFF_W2HI 13440
#define OFF_W2LO 19840
#define OFF_B2   26240
#define OFF_FCR  13440
#define SMEM_FLOATS 26304

__global__ __launch_bounds__(256, 2)
void head_kernel(const float* __restrict__ x,
                 const float* __restrict__ w1g, const float* __restrict__ b1g,
                 const float* __restrict__ w2g, const float* __restrict__ b2g,
                 const float* __restrict__ f1wg, const float* __restrict__ f1bg,
                 const float* __restrict__ f2wg, const float* __restrict__ f2bg,
                 float* __restrict__ out)
{
    extern __shared__ float sm[];
    float* zsh  = sm;
    float* y2sh = sm;                 // reuses zsh region after conv1
    float* hsh  = sm + OFF_HSH;
    float* y1sh = sm + OFF_Y1;
    float* w1sh = sm + OFF_W1;
    float* b1sh = sm + OFF_B1;
    float* w2hi = sm + OFF_W2HI;
    float* w2lo = sm + OFF_W2LO;
    float* b2sh = sm + OFF_B2;

    int tid  = threadIdx.x;
    int row0 = blockIdx.x * 32;       // global row = (b*T + t)*N + n

    // ---- stage 0: gather z tile + conv weights (w2 pre-split hi/lo) ----
    for (int i = tid; i < 4096; i += 256) {
        int r  = i & 31;
        int kf = i >> 5;
        int f  = kf >> 4;
        int k  = kf & 15;
        int R  = row0 + r;
        int n  = R % NN;
        int bt = R / NN;
        float v;
        if (k == 0) {
            v = x[(size_t)bt * ROWSTRIDE + f * NN + n];
        } else if ((bt & 63) < k) {
            v = 0.f;                  // triangular zero region (never stored)
        } else {
            v = g_z[(size_t)(k - 1) * SLAB + (size_t)bt * ROWSTRIDE + f * NN + n];
        }
        zsh[r * ZS + f * 16 + k] = v;
    }
    for (int i = tid; i < 1024; i += 256) w1sh[i] = w1g[i];
    if (tid < 32) b1sh[tid] = b1g[tid];
    for (int i = tid; i < 6144; i += 256) {
        int n = i / 96, k = i % 96;
        uint32_t hi, lo;
        tf32_split(w2g[i], hi, lo);
        w2hi[n * 100 + k] = __uint_as_float(hi);   // stride 100: banks 4*gr+tg
        w2lo[n * 100 + k] = __uint_as_float(lo);
    }
    if (tid < 64) b2sh[tid] = b2g[tid];
    __syncthreads();

    // ---- conv1 + relu + maxpool2 (scalar, proven) ----
    {
        int r = tid & 31, fg = tid >> 5;
        float acc[4][12];
        #pragma unroll
        for (int c = 0; c < 4; c++)
            #pragma unroll
            for (int l = 0; l < 12; l++) acc[c][l] = 0.f;

        #pragma unroll 2
        for (int f0 = 0; f0 < 8; f0++) {
            float a[16];
            #pragma unroll
            for (int i = 0; i < 16; i++) a[i] = zsh[r * ZS + f0 * 16 + i];
            #pragma unroll
            for (int kk = 0; kk < 4; kk++) {
                #pragma unroll
                for (int c = 0; c < 4; c++) {
                    float w = w1sh[(fg * 4 + c) * 32 + f0 * 4 + kk];
                    #pragma unroll
                    for (int l = 0; l < 12; l++)
                        acc[c][l] = fmaf(a[l + kk], w, acc[c][l]);
                }
            }
        }
        #pragma unroll
        for (int c = 0; c < 4; c++) {
            int f1 = fg * 4 + c;
            float bb = b1sh[f1];
            #pragma unroll
            for (int lp = 0; lp < 6; lp++) {
                float v0 = fmaxf(acc[c][2 * lp]     + bb, 0.f);
                float v1 = fmaxf(acc[c][2 * lp + 1] + bb, 0.f);
                y1sh[r * Y1S + f1 * 6 + lp] = fmaxf(v0, v1);
            }
        }
    }
    __syncthreads();

    // ---- conv2 via 3xTF32 mma.m16n8k8 + relu + pool2 ----
    // C[128,64] = A[128,96] x B[96,64]; A row = r*4+p (im2col of y1),
    // B[k][n] = w2[n][k]. Warp w = M-tile; 12 k-steps x 8 N-tiles x 3 MMA.
    {
        int lane = tid & 31, w = tid >> 5;
        int gr = lane >> 2, tg = lane & 3;
        int mt = w;

        float acc[8][4];
        #pragma unroll
        for (int nt = 0; nt < 8; nt++)
            #pragma unroll
            for (int s = 0; s < 4; s++) acc[nt][s] = 0.f;

        int rowA = 16 * mt + gr;          // rows rowA and rowA+8
        int rA = rowA >> 2, pA = rowA & 3;
        int rB = rA + 2;                  // (rowA+8)>>2 ; p identical

        for (int ks = 0; ks < 12; ks++) {
            int k0 = 8 * ks + tg;
            int k1 = k0 + 4;
            int o0 = (k0 / 3) * 6 + (k0 % 3);
            int o1 = (k1 / 3) * 6 + (k1 % 3);
            float a0f = y1sh[rA * Y1S + o0 + pA];
            float a1f = y1sh[rB * Y1S + o0 + pA];
            float a2f = y1sh[rA * Y1S + o1 + pA];
            float a3f = y1sh[rB * Y1S + o1 + pA];
            uint32_t ah0, al0, ah1, al1, ah2, al2, ah3, al3;
            tf32_split(a0f, ah0, al0);
            tf32_split(a1f, ah1, al1);
            tf32_split(a2f, ah2, al2);
            tf32_split(a3f, ah3, al3);

            #pragma unroll
            for (int nt = 0; nt < 8; nt++) {
                int nb = (nt * 8 + gr) * 100;
                uint32_t bh0 = __float_as_uint(w2hi[nb + k0]);
                uint32_t bh1 = __float_as_uint(w2hi[nb + k1]);
                uint32_t bl0 = __float_as_uint(w2lo[nb + k0]);
                uint32_t bl1 = __float_as_uint(w2lo[nb + k1]);
                mma_tf32(acc[nt][0], acc[nt][1], acc[nt][2], acc[nt][3],
                         ah0, ah1, ah2, ah3, bh0, bh1);
                mma_tf32(acc[nt][0], acc[nt][1], acc[nt][2], acc[nt][3],
                         al0, al1, al2, al3, bh0, bh1);
                mma_tf32(acc[nt][0], acc[nt][1], acc[nt][2], acc[nt][3],
                         ah0, ah1, ah2, ah3, bl0, bl1);
            }
        }
        __syncthreads();                  // zsh reads done long ago; y2 reuse OK

        // bias + relu + pool (p-pairs via shfl_xor 4), write y2sh[r*129 + d]
        #pragma unroll
        for (int nt = 0; nt < 8; nt++) {
            int n0 = nt * 8 + 2 * tg;
            float bias0 = b2sh[n0];
            float bias1 = b2sh[n0 + 1];
            float v0 = fmaxf(acc[nt][0] + bias0, 0.f);
            float v1 = fmaxf(acc[nt][1] + bias1, 0.f);
            float v2 = fmaxf(acc[nt][2] + bias0, 0.f);
            float v3 = fmaxf(acc[nt][3] + bias1, 0.f);
            float p0 = __shfl_xor_sync(0xffffffffu, v0, 4);
            float p1 = __shfl_xor_sync(0xffffffffu, v1, 4);
            float p2 = __shfl_xor_sync(0xffffffffu, v2, 4);
            float p3 = __shfl_xor_sync(0xffffffffu, v3, 4);
            if ((gr & 1) == 0) {
                int pp = (gr & 3) >> 1;
                int ra = 4 * mt + (gr >> 2);
                int rb = ra + 2;
                y2sh[ra * Y2S + n0 * 2 + pp]       = fmaxf(v0, p0);
                y2sh[ra * Y2S + (n0 + 1) * 2 + pp] = fmaxf(v1, p1);
                y2sh[rb * Y2S + n0 * 2 + pp]       = fmaxf(v2, p2);
                y2sh[rb * Y2S + (n0 + 1) * 2 + pp] = fmaxf(v3, p3);
            }
        }
    }
    __syncthreads();                      // y2 complete; w2hi/lo now dead

    // ---- stage fc weights into dead region ----
    {
        float* fcr = sm + OFF_FCR;
        for (int i = tid; i < 8192; i += 256) {
            int j = i >> 7, d = i & 127;
            fcr[j * 129 + d] = f1wg[i];
        }
        if (tid < 64) fcr[8256 + tid] = f1bg[tid];
        for (int i = tid; i < 320; i += 256) fcr[8320 + i] = f2wg[i];
        if (tid < 5) fcr[8640 + tid] = f2bg[tid];
    }
    __syncthreads();

    // ---- fc1 + relu : 128 threads, thread tile 4 rows x 4 hidden ----
    if (tid < 128) {
        const float* fc1sh = sm + OFF_FCR;
        const float* fb    = fc1sh + 8256;
        int rg = tid & 7;
        int hg = tid >> 3;
        float acc[4][4];
        #pragma unroll
        for (int i = 0; i < 4; i++)
            #pragma unroll
            for (int j = 0; j < 4; j++) acc[i][j] = 0.f;

        #pragma unroll 4
        for (int d = 0; d < 128; d++) {
            float a0 = y2sh[(rg * 4 + 0) * Y2S + d];
            float a1 = y2sh[(rg * 4 + 1) * Y2S + d];
            float a2 = y2sh[(rg * 4 + 2) * Y2S + d];
            float a3 = y2sh[(rg * 4 + 3) * Y2S + d];
            float w0 = fc1sh[(hg * 4 + 0) * 129 + d];
            float w1 = fc1sh[(hg * 4 + 1) * 129 + d];
            float w2 = fc1sh[(hg * 4 + 2) * 129 + d];
            float w3 = fc1sh[(hg * 4 + 3) * 129 + d];
            acc[0][0] = fmaf(a0, w0, acc[0][0]); acc[0][1] = fmaf(a0, w1, acc[0][1]);
            acc[0][2] = fmaf(a0, w2, acc[0][2]); acc[0][3] = fmaf(a0, w3, acc[0][3]);
            acc[1][0] = fmaf(a1, w0, acc[1][0]); acc[1][1] = fmaf(a1, w1, acc[1][1]);
            acc[1][2] = fmaf(a1, w2, acc[1][2]); acc[1][3] = fmaf(a1, w3, acc[1][3]);
            acc[2][0] = fmaf(a2, w0, acc[2][0]); acc[2][1] = fmaf(a2, w1, acc[2][1]);
            acc[2][2] = fmaf(a2, w2, acc[2][2]); acc[2][3] = fmaf(a2, w3, acc[2][3]);
            acc[3][0] = fmaf(a3, w0, acc[3][0]); acc[3][1] = fmaf(a3, w1, acc[3][1]);
            acc[3][2] = fmaf(a3, w2, acc[3][2]); acc[3][3] = fmaf(a3, w3, acc[3][3]);
        }
        #pragma unroll
        for (int i = 0; i < 4; i++)
            #pragma unroll
            for (int j = 0; j < 4; j++)
                hsh[(rg * 4 + i) * HS + hg * 4 + j] =
                    fmaxf(acc[i][j] + fb[hg * 4 + j], 0.f);
    }
    __syncthreads();

    // ---- fc2 + transposed output write: out[b,t,o,n] ----
    if (tid < 160) {
        const float* fc2w = sm + OFF_FCR + 8320;
        const float* fc2b = sm + OFF_FCR + 8640;
        int r = tid & 31, o = tid >> 5;
        float acc = fc2b[o];
        #pragma unroll 8
        for (int j = 0; j < 64; j++)
            acc = fmaf(hsh[r * HS + j], fc2w[o * 64 + j], acc);
        int R  = row0 + r;
        int n  = R % NN;
        int bt = R / NN;
        out[((size_t)bt * 5 + o) * NN + n] = acc;
    }
}

// ---------------------------------------------------------------------------
extern "C" void kernel_launch(void* const* d_in, const int* in_sizes, int n_in,
                              void* d_out, int out_size)
{
    const float* x   = (const float*)d_in[0];
    const float* S   = (const float*)d_in[1];
    const float* w1  = (const float*)d_in[2];
    const float* b1  = (const float*)d_in[3];
    const float* w2  = (const float*)d_in[4];
    const float* b2  = (const float*)d_in[5];
    const float* f1w = (const float*)d_in[6];
    const float* f1b = (const float*)d_in[7];
    const float* f2w = (const float*)d_in[8];
    const float* f2b = (const float*)d_in[9];
    float* out = (float*)d_out;

    for (int k = 1; k <= 15; k++)
        diffuse_step_kernel<<<BT, 128>>>(x, S, k);

    size_t smem = (size_t)SMEM_FLOATS * sizeof(float);
    cudaFuncSetAttribute(head_kernel,
                         cudaFuncAttributeMaxDynamicSharedMemorySize, (int)smem);
    head_kernel<<<(NB * NT * NN) / 32, 256, smem>>>(
        x, w1, b1, w2, b2, f1w, f1b, f2w, f2b, out);
}

// round 15
// speedup vs baseline: 1.1207x; 1.0021x over previous
#include <cuda_runtime.h>
#include <cstddef>
#include <cstdint>

// Problem constants
#define NB   16
#define NT   64
#define NF0  8
#define NN   100
#define BT   (NB * NT)            // 1024
#define ROWSTRIDE (NF0 * NN)      // 800 floats per (b,t) slice
#define SLAB ((size_t)BT * ROWSTRIDE)  // 819200 floats per k-slab

__device__ float g_z[15 * BT * ROWSTRIDE];   // slabs k=1..15 (~49 MB)

// ---- packed f32x2 helpers (diffusion only) ----
typedef unsigned long long ull;
__device__ __forceinline__ ull pack2(float lo, float hi) {
    ull r; asm("mov.b64 %0, {%1,%2};" : "=l"(r) : "f"(lo), "f"(hi)); return r;
}
__device__ __forceinline__ void unpack2(ull v, float& lo, float& hi) {
    asm("mov.b64 {%0,%1}, %2;" : "=f"(lo), "=f"(hi) : "l"(v));
}
__device__ __forceinline__ ull ffma2(ull a, ull b, ull c) {
    ull d; asm("fma.rn.f32x2 %0, %1, %2, %3;" : "=l"(d) : "l"(a), "l"(b), "l"(c));
    return d;
}

// ---- tf32 helpers ----
__device__ __forceinline__ uint32_t tf32_of(float x) {
    uint32_t u; asm("cvt.rna.tf32.f32 %0, %1;" : "=r"(u) : "f"(x)); return u;
}
__device__ __forceinline__ void tf32_split(float x, uint32_t& hi, uint32_t& lo) {
    hi = tf32_of(x);
    lo = tf32_of(x - __uint_as_float(hi));
}
__device__ __forceinline__ void mma_tf32(
    float& d0, float& d1, float& d2, float& d3,
    uint32_t a0, uint32_t a1, uint32_t a2, uint32_t a3,
    uint32_t b0, uint32_t b1)
{
    asm volatile(
        "mma.sync.aligned.m16n8k8.row.col.f32.tf32.tf32.f32 "
        "{%0,%1,%2,%3}, {%4,%5,%6,%7}, {%8,%9}, {%0,%1,%2,%3};"
        : "+f"(d0), "+f"(d1), "+f"(d2), "+f"(d3)
        : "r"(a0), "r"(a1), "r"(a2), "r"(a3), "r"(b0), "r"(b1));
}
// 3-term split MMA: hi*hi + lo*hi + hi*lo (~fp32 accuracy)
__device__ __forceinline__ void mma3(
    float* c,
    uint32_t ah0, uint32_t al0, uint32_t ah1, uint32_t al1,
    uint32_t ah2, uint32_t al2, uint32_t ah3, uint32_t al3,
    uint32_t bh0, uint32_t bl0, uint32_t bh1, uint32_t bl1)
{
    mma_tf32(c[0], c[1], c[2], c[3], ah0, ah1, ah2, ah3, bh0, bh1);
    mma_tf32(c[0], c[1], c[2], c[3], al0, al1, al2, al3, bh0, bh1);
    mma_tf32(c[0], c[1], c[2], c[3], ah0, ah1, ah2, ah3, bl0, bl1);
}

// ---------------------------------------------------------------------------
// Diffusion step k (R9 version — measured best)
// ---------------------------------------------------------------------------
__global__ __launch_bounds__(128)
void diffuse_step_kernel(const float* __restrict__ x,
                         const float* __restrict__ S,
                         int k)
{
    int bt  = blockIdx.x;
    int t   = bt & 63;
    if (t < k) return;
    int tid = threadIdx.x;

    const float* src = (k == 1)
        ? (x + (size_t)(bt - 1) * ROWSTRIDE)
        : (g_z + (size_t)(k - 2) * SLAB + (size_t)(bt - 1) * ROWSTRIDE);

    __shared__ float At[NN * NF0];            // [n][f]
    for (int i = tid; i < ROWSTRIDE; i += 128) {
        int f = i / NN, n = i % NN;
        At[n * 8 + f] = src[i];
    }
    __syncthreads();

    if (tid < 100) {
        int m = tid;
        const float* Sp = S + (size_t)bt * (NN * NN) + m;

        ull a01 = 0ull, a23 = 0ull, a45 = 0ull, a67 = 0ull;
        #pragma unroll 4
        for (int n = 0; n < NN; n++) {
            float s = Sp[(size_t)n * NN];
            ull s2 = pack2(s, s);
            const ull* ar = reinterpret_cast<const ull*>(At + n * 8);
            a01 = ffma2(ar[0], s2, a01);
            a23 = ffma2(ar[1], s2, a23);
            a45 = ffma2(ar[2], s2, a45);
            a67 = ffma2(ar[3], s2, a67);
        }
        float* dst = g_z + (size_t)(k - 1) * SLAB + (size_t)bt * ROWSTRIDE + m;
        float v0, v1;
        unpack2(a01, v0, v1); dst[0 * NN] = v0; dst[1 * NN] = v1;
        unpack2(a23, v0, v1); dst[2 * NN] = v0; dst[3 * NN] = v1;
        unpack2(a45, v0, v1); dst[4 * NN] = v0; dst[5 * NN] = v1;
        unpack2(a67, v0, v1); dst[6 * NN] = v0; dst[7 * NN] = v1;
    }
}

// ---------------------------------------------------------------------------
// Fused head: ALL THREE GEMM STAGES ON 3xTF32 MMA (conv1, conv2, fc1);
// fc2 scalar. 32 rows/block, 256 threads (8 warps), 2 blocks/SM.
//
// Smem (floats):
//  [0,4128)       zsh (32x129)  -> reused as y2sh (32x129)
//  [4128,6208)    hsh (32x65)
//  [6208,12384)   y1sh (32x193)
//  [12384,13536)  w1sh fp32 [n*36+k]  (32 ch x 32 k, padded)
//  [13568,19968)  w2hi (64x100 tf32)  } dead after conv2; overlay:
//  [19968,26368)  w2lo (64x100 tf32)  } fc1w fp32 @13568 [n*132+d] (8448),
//  [26368,26432)  b2                    fc1b @+8448, fc2w @+8512, fc2b @+8832
//  [26432,26464)  b1
// ---------------------------------------------------------------------------
#define ZS   129
#define Y1S  193
#define Y2S  129
#define HS   65
#define OFF_HSH  4128
#define OFF_Y1   6208
#define OFF_W1   12384
#define OFF_W2HI 13568
#define OFF_W2LO 19968
#define OFF_B2   26368
#define OFF_B1   26432
#define OFF_FCR  13568
#define SMEM_FLOATS 26464

__global__ __launch_bounds__(256, 2)
void head_kernel(const float* __restrict__ x,
                 const float* __restrict__ w1g, const float* __restrict__ b1g,
                 const float* __restrict__ w2g, const float* __restrict__ b2g,
                 const float* __restrict__ f1wg, const float* __restrict__ f1bg,
                 const float* __restrict__ f2wg, const float* __restrict__ f2bg,
                 float* __restrict__ out)
{
    extern __shared__ float sm[];
    float* zsh  = sm;
    float* y2sh = sm;                 // reuses zsh region after conv1
    float* hsh  = sm + OFF_HSH;
    float* y1sh = sm + OFF_Y1;
    float* w1sh = sm + OFF_W1;
    float* w2hi = sm + OFF_W2HI;
    float* w2lo = sm + OFF_W2LO;
    float* b2sh = sm + OFF_B2;
    float* b1sh = sm + OFF_B1;

    int tid  = threadIdx.x;
    int row0 = blockIdx.x * 32;       // global row = (b*T + t)*N + n
    int lane = tid & 31, wrp = tid >> 5;
    int gr = lane >> 2, tg = lane & 3;

    // ---- stage 0: gather z tile + conv weights ----
    for (int i = tid; i < 4096; i += 256) {
        int r  = i & 31;
        int kf = i >> 5;
        int f  = kf >> 4;
        int k  = kf & 15;
        int R  = row0 + r;
        int n  = R % NN;
        int bt = R / NN;
        float v;
        if (k == 0) {
            v = x[(size_t)bt * ROWSTRIDE + f * NN + n];
        } else if ((bt & 63) < k) {
            v = 0.f;                  // triangular zero region (never stored)
        } else {
            v = g_z[(size_t)(k - 1) * SLAB + (size_t)bt * ROWSTRIDE + f * NN + n];
        }
        zsh[r * ZS + f * 16 + k] = v;
    }
    for (int i = tid; i < 1024; i += 256) {
        int n = i >> 5, k = i & 31;
        w1sh[n * 36 + k] = w1g[i];    // padded stride 36: bank 4n+k
    }
    if (tid < 32) b1sh[tid] = b1g[tid];
    for (int i = tid; i < 6144; i += 256) {
        int n = i / 96, k = i % 96;
        uint32_t hi, lo;
        tf32_split(w2g[i], hi, lo);
        w2hi[n * 100 + k] = __uint_as_float(hi);
        w2lo[n * 100 + k] = __uint_as_float(lo);
    }
    if (tid < 64) b2sh[tid] = b2g[tid];
    __syncthreads();

    // ---- conv1 via 3xTF32 MMA + relu + pool2 ----
    // C[384,32] = A[384,32] x B[32,32]; A row = r*12+p (im2col of z),
    // A[row][k] = zsh[r*ZS + (k>>2)*16 + (k&3) + p]. B[k][n] = w1[n][k].
    // Warp handles M-tiles {w, w+8, w+16}; 4 N-tiles x 4 k-steps x 3 MMA.
    {
        #pragma unroll
        for (int i3 = 0; i3 < 3; i3++) {
            int mt = wrp + 8 * i3;
            int rowLo = 16 * mt + gr;
            int rowHi = rowLo + 8;
            int rLo = rowLo / 12, pLo = rowLo % 12;
            int rHi = rowHi / 12, pHi = rowHi % 12;

            float acc[4][4];
            #pragma unroll
            for (int nt = 0; nt < 4; nt++)
                #pragma unroll
                for (int s = 0; s < 4; s++) acc[nt][s] = 0.f;

            #pragma unroll
            for (int ks = 0; ks < 4; ks++) {
                // k0 = 8ks+tg -> f0=2ks, kk=tg ; k1 = k0+4 -> f0=2ks+1, kk=tg
                float a0f = zsh[rLo * ZS + (2 * ks) * 16 + tg + pLo];
                float a1f = zsh[rHi * ZS + (2 * ks) * 16 + tg + pHi];
                float a2f = zsh[rLo * ZS + (2 * ks + 1) * 16 + tg + pLo];
                float a3f = zsh[rHi * ZS + (2 * ks + 1) * 16 + tg + pHi];
                uint32_t ah0, al0, ah1, al1, ah2, al2, ah3, al3;
                tf32_split(a0f, ah0, al0);
                tf32_split(a1f, ah1, al1);
                tf32_split(a2f, ah2, al2);
                tf32_split(a3f, ah3, al3);

                #pragma unroll
                for (int nt = 0; nt < 4; nt++) {
                    int n = nt * 8 + gr;
                    float b0f = w1sh[n * 36 + 8 * ks + tg];
                    float b1f = w1sh[n * 36 + 8 * ks + tg + 4];
                    uint32_t bh0, bl0, bh1, bl1;
                    tf32_split(b0f, bh0, bl0);
                    tf32_split(b1f, bh1, bl1);
                    mma3(acc[nt], ah0, al0, ah1, al1, ah2, al2, ah3, al3,
                         bh0, bl0, bh1, bl1);
                }
            }
            // epilogue: bias+relu, pool adjacent rows (gr even <-> gr+1)
            #pragma unroll
            for (int nt = 0; nt < 4; nt++) {
                int f1a = nt * 8 + 2 * tg;
                float ba = b1sh[f1a], bb = b1sh[f1a + 1];
                float v0 = fmaxf(acc[nt][0] + ba, 0.f);
                float v1 = fmaxf(acc[nt][1] + bb, 0.f);
                float v2 = fmaxf(acc[nt][2] + ba, 0.f);
                float v3 = fmaxf(acc[nt][3] + bb, 0.f);
                float p0 = __shfl_xor_sync(0xffffffffu, v0, 4);
                float p1 = __shfl_xor_sync(0xffffffffu, v1, 4);
                float p2 = __shfl_xor_sync(0xffffffffu, v2, 4);
                float p3 = __shfl_xor_sync(0xffffffffu, v3, 4);
                if ((gr & 1) == 0) {
                    int lpLo = pLo >> 1;       // rowLo even => pLo even
                    int lpHi = pHi >> 1;
                    y1sh[rLo * Y1S + f1a * 6 + lpLo]       = fmaxf(v0, p0);
                    y1sh[rLo * Y1S + (f1a + 1) * 6 + lpLo] = fmaxf(v1, p1);
                    y1sh[rHi * Y1S + f1a * 6 + lpHi]       = fmaxf(v2, p2);
                    y1sh[rHi * Y1S + (f1a + 1) * 6 + lpHi] = fmaxf(v3, p3);
                }
            }
        }
    }
    __syncthreads();

    // ---- conv2 via 3xTF32 MMA + relu + pool2 (R14 proven) ----
    {
        int mt = wrp;
        float acc[8][4];
        #pragma unroll
        for (int nt = 0; nt < 8; nt++)
            #pragma unroll
            for (int s = 0; s < 4; s++) acc[nt][s] = 0.f;

        int rowA = 16 * mt + gr;
        int rA = rowA >> 2, pA = rowA & 3;
        int rB = rA + 2;

        for (int ks = 0; ks < 12; ks++) {
            int k0 = 8 * ks + tg;
            int k1 = k0 + 4;
            int o0 = (k0 / 3) * 6 + (k0 % 3);
            int o1 = (k1 / 3) * 6 + (k1 % 3);
            float a0f = y1sh[rA * Y1S + o0 + pA];
            float a1f = y1sh[rB * Y1S + o0 + pA];
            float a2f = y1sh[rA * Y1S + o1 + pA];
            float a3f = y1sh[rB * Y1S + o1 + pA];
            uint32_t ah0, al0, ah1, al1, ah2, al2, ah3, al3;
            tf32_split(a0f, ah0, al0);
            tf32_split(a1f, ah1, al1);
            tf32_split(a2f, ah2, al2);
            tf32_split(a3f, ah3, al3);

            #pragma unroll
            for (int nt = 0; nt < 8; nt++) {
                int nb = (nt * 8 + gr) * 100;
                uint32_t bh0 = __float_as_uint(w2hi[nb + k0]);
                uint32_t bh1 = __float_as_uint(w2hi[nb + k1]);
                uint32_t bl0 = __float_as_uint(w2lo[nb + k0]);
                uint32_t bl1 = __float_as_uint(w2lo[nb + k1]);
                mma3(acc[nt], ah0, al0, ah1, al1, ah2, al2, ah3, al3,
                     bh0, bl0, bh1, bl1);
            }
        }
        __syncthreads();                  // all y1/zsh reads done; y2 reuse OK

        #pragma unroll
        for (int nt = 0; nt < 8; nt++) {
            int n0 = nt * 8 + 2 * tg;
            float bias0 = b2sh[n0];
            float bias1 = b2sh[n0 + 1];
            float v0 = fmaxf(acc[nt][0] + bias0, 0.f);
            float v1 = fmaxf(acc[nt][1] + bias1, 0.f);
            float v2 = fmaxf(acc[nt][2] + bias0, 0.f);
            float v3 = fmaxf(acc[nt][3] + bias1, 0.f);
            float p0 = __shfl_xor_sync(0xffffffffu, v0, 4);
            float p1 = __shfl_xor_sync(0xffffffffu, v1, 4);
            float p2 = __shfl_xor_sync(0xffffffffu, v2, 4);
            float p3 = __shfl_xor_sync(0xffffffffu, v3, 4);
            if ((gr & 1) == 0) {
                int pp = (gr & 3) >> 1;
                int ra = 4 * mt + (gr >> 2);
                int rb = ra + 2;
                y2sh[ra * Y2S + n0 * 2 + pp]       = fmaxf(v0, p0);
                y2sh[ra * Y2S + (n0 + 1) * 2 + pp] = fmaxf(v1, p1);
                y2sh[rb * Y2S + n0 * 2 + pp]       = fmaxf(v2, p2);
                y2sh[rb * Y2S + (n0 + 1) * 2 + pp] = fmaxf(v3, p3);
            }
        }
    }
    __syncthreads();                      // y2 complete; w2hi/lo dead

    // ---- stage fc weights (fp32) into dead region ----
    {
        float* fcr = sm + OFF_FCR;
        for (int i = tid; i < 8192; i += 256) {
            int j = i >> 7, d = i & 127;
            fcr[j * 132 + d] = f1wg[i];   // stride 132: bank 4n+d
        }
        if (tid < 64) fcr[8448 + tid] = f1bg[tid];
        for (int i = tid; i < 320; i += 256) fcr[8512 + i] = f2wg[i];
        if (tid < 5) fcr[8832 + tid] = f2bg[tid];
    }
    __syncthreads();

    // ---- fc1 via 3xTF32 MMA + relu ----
    // C[32,64] = y2[32,128] x fc1w^T; warp = (mt = w&1, nt in {2(w>>1),+1})
    {
        const float* fcr = sm + OFF_FCR;
        const float* fb  = fcr + 8448;
        int mt  = wrp & 1;
        int nt0 = (wrp >> 1) * 2;
        int rowA = 16 * mt + gr;

        float acc[2][4];
        #pragma unroll
        for (int q = 0; q < 2; q++)
            #pragma unroll
            for (int s = 0; s < 4; s++) acc[q][s] = 0.f;

        for (int ks = 0; ks < 16; ks++) {
            int k0 = 8 * ks + tg;
            int k1 = k0 + 4;
            float a0f = y2sh[rowA * Y2S + k0];
            float a1f = y2sh[(rowA + 8) * Y2S + k0];
            float a2f = y2sh[rowA * Y2S + k1];
            float a3f = y2sh[(rowA + 8) * Y2S + k1];
            uint32_t ah0, al0, ah1, al1, ah2, al2, ah3, al3;
            tf32_split(a0f, ah0, al0);
            tf32_split(a1f, ah1, al1);
            tf32_split(a2f, ah2, al2);
            tf32_split(a3f, ah3, al3);

            #pragma unroll
            for (int q = 0; q < 2; q++) {
                int n = (nt0 + q) * 8 + gr;
                float b0f = fcr[n * 132 + k0];
                float b1f = fcr[n * 132 + k1];
                uint32_t bh0, bl0, bh1, bl1;
                tf32_split(b0f, bh0, bl0);
                tf32_split(b1f, bh1, bl1);
                mma3(acc[q], ah0, al0, ah1, al1, ah2, al2, ah3, al3,
                     bh0, bl0, bh1, bl1);
            }
        }
        #pragma unroll
        for (int q = 0; q < 2; q++) {
            int n0 = (nt0 + q) * 8 + 2 * tg;
            float ba = fb[n0], bb = fb[n0 + 1];
            hsh[rowA * HS + n0]           = fmaxf(acc[q][0] + ba, 0.f);
            hsh[rowA * HS + n0 + 1]       = fmaxf(acc[q][1] + bb, 0.f);
            hsh[(rowA + 8) * HS + n0]     = fmaxf(acc[q][2] + ba, 0.f);
            hsh[(rowA + 8) * HS + n0 + 1] = fmaxf(acc[q][3] + bb, 0.f);
        }
    }
    __syncthreads();

    // ---- fc2 + transposed output write: out[b,t,o,n] ----
    if (tid < 160) {
        const float* fc2w = sm + OFF_FCR + 8512;
        const float* fc2b = sm + OFF_FCR + 8832;
        int r = tid & 31, o = tid >> 5;
        float acc = fc2b[o];
        #pragma unroll 8
        for (int j = 0; j < 64; j++)
            acc = fmaf(hsh[r * HS + j], fc2w[o * 64 + j], acc);
        int R  = row0 + r;
        int n  = R % NN;
        int bt = R / NN;
        out[((size_t)bt * 5 + o) * NN + n] = acc;
    }
}

// ---------------------------------------------------------------------------
extern "C" void kernel_launch(void* const* d_in, const int* in_sizes, int n_in,
                              void* d_out, int out_size)
{
    const float* x   = (const float*)d_in[0];
    const float* S   = (const float*)d_in[1];
    const float* w1  = (const float*)d_in[2];
    const float* b1  = (const float*)d_in[3];
    const float* w2  = (const float*)d_in[4];
    const float* b2  = (const float*)d_in[5];
    const float* f1w = (const float*)d_in[6];
    const float* f1b = (const float*)d_in[7];
    const float* f2w = (const float*)d_in[8];
    const float* f2b = (const float*)d_in[9];
    float* out = (float*)d_out;

    for (int k = 1; k <= 15; k++)
        diffuse_step_kernel<<<BT, 128>>>(x, S, k);

    size_t smem = (size_t)SMEM_FLOATS * sizeof(float);
    cudaFuncSetAttribute(head_kernel,
                         cudaFuncAttributeMaxDynamicSharedMemorySize, (int)smem);
    head_kernel<<<(NB * NT * NN) / 32, 256, smem>>>(
        x, w1, b1, w2, b2, f1w, f1b, f2w, f2b, out);
}